// round 5
// baseline (speedup 1.0000x reference)
#include <cuda_runtime.h>
#include <cstdint>

// ---------------------------------------------------------------------------
// Problem constants
//   B=8, Cf=512, Cg=256, HID=256, Co=256, H=W=64, HW=4096, pool 16x16 -> 16 KV
// ---------------------------------------------------------------------------
#define HW    4096
#define NB    8
#define HIDN  256

// ---------------------------------------------------------------------------
// Device scratch (no allocation allowed -> __device__ globals)
// ---------------------------------------------------------------------------
__device__ float g_wqf[512 * 256];          // gamma-folded wq
__device__ float g_wkf[256 * 256];
__device__ float g_wvf[256 * 256];
__device__ float g_Sq[256], g_Tq[256];
__device__ float g_Sk[256], g_Tk[256];
__device__ float g_Svv[256], g_Tvv[256];
__device__ float g_fs[256], g_fb[256];      // folded BN scale/shift (incl outc_b)
__device__ float g_rf[NB * HW], g_af[NB * HW];   // e_f LN: rstd, -rstd*mean
__device__ float g_rg[NB * HW], g_ag[NB * HW];   // e_g LN
__device__ float g_q   [NB * 256 * HW];
__device__ float g_k   [NB * 256 * HW];
__device__ float g_v   [NB * 256 * HW];
__device__ float g_a   [NB * 256 * HW];     // attention output
__device__ float g_cin [NB * 256 * HW];     // dwconv + attn
__device__ float g_comb[NB * 256 * HW];     // wo projection
__device__ float g_efp [NB * 256 * HW];     // 1x1 proj of e_f
__device__ float g_kp[NB * 16 * 256];       // pooled K
__device__ float g_vp[NB * 16 * 256];       // pooled V

// ---------------------------------------------------------------------------
// Prep: fold LN gammas into weights, compute S/T vectors, fold BN
// ---------------------------------------------------------------------------
__global__ void prep_kernel(const float* __restrict__ wq, const float* __restrict__ bq,
                            const float* __restrict__ gf, const float* __restrict__ bf,
                            const float* __restrict__ wk, const float* __restrict__ bk,
                            const float* __restrict__ gg, const float* __restrict__ bg,
                            const float* __restrict__ wv, const float* __restrict__ bv,
                            const float* __restrict__ outc_b,
                            const float* __restrict__ bn_g, const float* __restrict__ bn_b,
                            const float* __restrict__ bn_m, const float* __restrict__ bn_v)
{
    int j = threadIdx.x;  // 0..255
    if (blockIdx.x == 0) {
        float S = 0.f, T = 0.f;
        for (int c = 0; c < 512; c++) {
            float w = wq[c * 256 + j];
            float f = w * gf[c];
            g_wqf[c * 256 + j] = f;
            S += f; T += w * bf[c];
        }
        g_Sq[j] = S; g_Tq[j] = T + bq[j];
    } else if (blockIdx.x == 1) {
        float S = 0.f, T = 0.f;
        for (int c = 0; c < 256; c++) {
            float w = wk[c * 256 + j];
            float f = w * gg[c];
            g_wkf[c * 256 + j] = f;
            S += f; T += w * bg[c];
        }
        g_Sk[j] = S; g_Tk[j] = T + bk[j];
    } else if (blockIdx.x == 2) {
        float S = 0.f, T = 0.f;
        for (int c = 0; c < 256; c++) {
            float w = wv[c * 256 + j];
            float f = w * gg[c];
            g_wvf[c * 256 + j] = f;
            S += f; T += w * bg[c];
        }
        g_Svv[j] = S; g_Tvv[j] = T + bv[j];
    } else {
        float sc = bn_g[j] * rsqrtf(bn_v[j] + 1e-5f);
        g_fs[j] = sc;
        g_fb[j] = (outc_b[j] - bn_m[j]) * sc + bn_b[j];
    }
}

// ---------------------------------------------------------------------------
// Per-pixel LN statistics over the channel dim. NCHW: threads = adjacent
// pixels -> every channel pass is a fully coalesced load.
// ---------------------------------------------------------------------------
template <int WHICH>
__global__ void stats_kernel(const float* __restrict__ X)
{
    constexpr int C = (WHICH == 0) ? 512 : 256;
    int gid = blockIdx.x * 256 + threadIdx.x;        // 0..32767
    const float* base = X + (size_t)(gid >> 12) * C * HW + (gid & (HW - 1));
    float s = 0.f, s2 = 0.f;
#pragma unroll 8
    for (int c = 0; c < C; c++) {
        float v = base[(size_t)c * HW];
        s += v; s2 = fmaf(v, v, s2);
    }
    const float invC = 1.0f / (float)C;
    float m = s * invC;
    float var = fmaf(-m, m, s2 * invC);
    float r = rsqrtf(var + 1e-5f);
    if (WHICH == 0) { g_rf[gid] = r; g_af[gid] = -r * m; }
    else            { g_rg[gid] = r; g_ag[gid] = -r * m; }
}

// ---------------------------------------------------------------------------
// Generic tiled fp32 GEMM: C[j][p] = sum_c W[c][j] * X[c][p], 64x64x16 tile,
// 256 threads, 4x4 microtile, fused per-CFG prologue/epilogue:
//   CFG 0/1/2 : LN-folded epilogue  r_p*acc + a_p*S_j + T_j   (q/k/v)
//   CFG 3     : plain + bias                                   (wo)
//   CFG 4     : plain + bias, W transposed [j][c]              (efp)
//   CFG 5     : gated (X * g_comb) + BN + ReLU, W transposed   (final out)
// ---------------------------------------------------------------------------
template <int CFG>
__global__ __launch_bounds__(256)
void gemm_kernel(const float* __restrict__ Wext,
                 const float* __restrict__ Xext,
                 const float* __restrict__ Bext,
                 float* __restrict__ Cext,
                 int K)
{
    constexpr int  MODE = (CFG <= 2) ? 0 : ((CFG <= 4) ? 1 : 2);
    constexpr bool WT   = (CFG >= 4);

    const float* W = (CFG == 0) ? g_wqf : (CFG == 1) ? g_wkf : (CFG == 2) ? g_wvf : Wext;
    const float* X = (CFG == 3) ? g_cin : (CFG == 5) ? g_efp : Xext;
    float*       C = (CFG == 0) ? g_q   : (CFG == 1) ? g_k   : (CFG == 2) ? g_v
                   : (CFG == 3) ? g_comb: (CFG == 4) ? g_efp : Cext;

    const int b  = blockIdx.z;
    const int pb = blockIdx.x * 64;
    const int jb = blockIdx.y * 64;
    const float* Xb = X + (size_t)b * K * HW;

    __shared__ __align__(16) float As[16][64];
    __shared__ __align__(16) float Xs[16][64];

    const int tid = threadIdx.x;
    const int tx  = tid & 15;
    const int ty  = tid >> 4;
    float acc[4][4] = {};

    for (int kt = 0; kt < K; kt += 16) {
        if (!WT) {
            int kk = tid >> 4, j4 = (tid & 15) << 2;
            float4 wv = *(const float4*)(W + (size_t)(kt + kk) * 256 + jb + j4);
            *(float4*)&As[kk][j4] = wv;
        } else {
            int j = tid >> 2, kq = (tid & 3) << 2;
            float4 wv = *(const float4*)(W + (size_t)(jb + j) * K + kt + kq);
            As[kq + 0][j] = wv.x; As[kq + 1][j] = wv.y;
            As[kq + 2][j] = wv.z; As[kq + 3][j] = wv.w;
        }
        {
            int kk = tid >> 4, p4 = (tid & 15) << 2;
            size_t off = (size_t)(kt + kk) * HW + pb + p4;
            float4 xv = *(const float4*)(Xb + off);
            if (MODE == 2) {
                const float* X2b = g_comb + (size_t)b * 256 * HW;
                float4 yv = *(const float4*)(X2b + off);
                xv.x *= yv.x; xv.y *= yv.y; xv.z *= yv.z; xv.w *= yv.w;
            }
            *(float4*)&Xs[kk][p4] = xv;
        }
        __syncthreads();
#pragma unroll
        for (int kk = 0; kk < 16; kk++) {
            float av[4], bv[4];
#pragma unroll
            for (int i = 0; i < 4; i++) av[i] = As[kk][ty + 16 * i];
#pragma unroll
            for (int l = 0; l < 4; l++) bv[l] = Xs[kk][tx + 16 * l];
#pragma unroll
            for (int i = 0; i < 4; i++)
#pragma unroll
                for (int l = 0; l < 4; l++)
                    acc[i][l] = fmaf(av[i], bv[l], acc[i][l]);
        }
        __syncthreads();
    }

    float* Cb = C + (size_t)b * 256 * HW;
    if (MODE == 0) {
        const float* rv  = (CFG == 0) ? g_rf : g_rg;
        const float* avv = (CFG == 0) ? g_af : g_ag;
        const float* Sv  = (CFG == 0) ? g_Sq : (CFG == 1) ? g_Sk : g_Svv;
        const float* Tv  = (CFG == 0) ? g_Tq : (CFG == 1) ? g_Tk : g_Tvv;
        float rr[4], aa[4];
#pragma unroll
        for (int l = 0; l < 4; l++) {
            int p = pb + tx + 16 * l;
            rr[l] = rv [b * HW + p];
            aa[l] = avv[b * HW + p];
        }
#pragma unroll
        for (int i = 0; i < 4; i++) {
            int j = jb + ty + 16 * i;
            float S = Sv[j], T = Tv[j];
#pragma unroll
            for (int l = 0; l < 4; l++) {
                int p = pb + tx + 16 * l;
                Cb[(size_t)j * HW + p] = fmaf(rr[l], acc[i][l], fmaf(aa[l], S, T));
            }
        }
    } else if (MODE == 1) {
#pragma unroll
        for (int i = 0; i < 4; i++) {
            int j = jb + ty + 16 * i;
            float bb = Bext[j];
#pragma unroll
            for (int l = 0; l < 4; l++) {
                int p = pb + tx + 16 * l;
                Cb[(size_t)j * HW + p] = acc[i][l] + bb;
            }
        }
    } else {
#pragma unroll
        for (int i = 0; i < 4; i++) {
            int j = jb + ty + 16 * i;
            float fs = g_fs[j], fb = g_fb[j];
#pragma unroll
            for (int l = 0; l < 4; l++) {
                int p = pb + tx + 16 * l;
                float v = fmaf(acc[i][l], fs, fb);
                Cb[(size_t)j * HW + p] = fmaxf(v, 0.0f);
            }
        }
    }
}

// ---------------------------------------------------------------------------
// 16x16 max-pool (K) + avg-pool (V). Block = (batch, cell-row); thread covers
// (channel, cell-col); float4 rows keep the 512B warp transaction dense.
// ---------------------------------------------------------------------------
__global__ void pool_kernel()
{
    int bc = blockIdx.x;         // 0..31  (b*4 + cell_row)
    int b  = bc >> 2;
    int ch = bc & 3;
    int d0 = threadIdx.x >> 2;   // 0..63
    int cw = threadIdx.x & 3;    // 0..3

    for (int dc = 0; dc < 4; dc++) {
        int d = dc * 64 + d0;
        size_t base = (size_t)(b * 256 + d) * HW + (size_t)(ch * 16) * 64 + cw * 16;
        float mx = -3.4e38f, sm = 0.f;
        for (int hh = 0; hh < 16; hh++) {
            const float4* kr = (const float4*)(g_k + base + hh * 64);
            const float4* vr = (const float4*)(g_v + base + hh * 64);
#pragma unroll
            for (int i = 0; i < 4; i++) {
                float4 kv = kr[i], vv = vr[i];
                mx = fmaxf(mx, fmaxf(fmaxf(kv.x, kv.y), fmaxf(kv.z, kv.w)));
                sm += (vv.x + vv.y) + (vv.z + vv.w);
            }
        }
        int cell = ch * 4 + cw;
        g_kp[(b * 16 + cell) * 256 + d] = mx;
        g_vp[(b * 16 + cell) * 256 + d] = sm * (1.0f / 256.0f);
    }
}

// ---------------------------------------------------------------------------
// Pooled attention: 16 KV tokens in SMEM, thread = one query pixel.
// ---------------------------------------------------------------------------
__global__ __launch_bounds__(256)
void attn_kernel()
{
    __shared__ float ks[4096];
    __shared__ float vs[4096];
    int b   = blockIdx.y;
    int pix = blockIdx.x * 256 + threadIdx.x;

    for (int i = threadIdx.x; i < 4096; i += 256) {
        ks[i] = g_kp[b * 4096 + i];
        vs[i] = g_vp[b * 4096 + i];
    }
    __syncthreads();

    float s[16];
#pragma unroll
    for (int t = 0; t < 16; t++) s[t] = 0.f;

    const float* qb = g_q + (size_t)b * 256 * HW + pix;
    for (int d = 0; d < 256; d++) {
        float qd = qb[(size_t)d * HW];
#pragma unroll
        for (int t = 0; t < 16; t++)
            s[t] = fmaf(qd, ks[t * 256 + d], s[t]);
    }
    float m = -3.4e38f;
#pragma unroll
    for (int t = 0; t < 16; t++) { s[t] *= 0.0625f; m = fmaxf(m, s[t]); }
    float sum = 0.f;
#pragma unroll
    for (int t = 0; t < 16; t++) { s[t] = __expf(s[t] - m); sum += s[t]; }
    float inv = 1.0f / sum;
#pragma unroll
    for (int t = 0; t < 16; t++) s[t] *= inv;

    float* ab = g_a + (size_t)b * 256 * HW + pix;
    for (int d = 0; d < 256; d++) {
        float acc = 0.f;
#pragma unroll
        for (int t = 0; t < 16; t++)
            acc = fmaf(s[t], vs[t * 256 + d], acc);
        ab[(size_t)d * HW] = acc;
    }
}

// ---------------------------------------------------------------------------
// Depthwise 3x3 on Q (cross-correlation, zero pad) + attention add.
// Each thread handles 4 consecutive pixels in one row -> kernel-row loads are
// reused across the 4 outputs and launch count drops 4x.
// ---------------------------------------------------------------------------
__global__ __launch_bounds__(256)
void dwadd_kernel(const float* __restrict__ dwk)
{
    int bc   = blockIdx.y;             // b*256 + c
    int c    = bc & 255;
    int pix0 = (blockIdx.x * 256 + threadIdx.x) * 4;   // 4 pixels per thread
    int h = pix0 >> 6, w0 = pix0 & 63;

    float k0 = dwk[c * 9 + 0], k1 = dwk[c * 9 + 1], k2 = dwk[c * 9 + 2];
    float k3 = dwk[c * 9 + 3], k4 = dwk[c * 9 + 4], k5 = dwk[c * 9 + 5];
    float k6 = dwk[c * 9 + 6], k7 = dwk[c * 9 + 7], k8 = dwk[c * 9 + 8];

    const float* qc = g_q + (size_t)bc * HW;
    const float* ac = g_a + (size_t)bc * HW;
    float*       oc = g_cin + (size_t)bc * HW;

    float acc[4];
#pragma unroll
    for (int i = 0; i < 4; i++) acc[i] = ac[pix0 + i];

#pragma unroll
    for (int dy = -1; dy <= 1; dy++) {
        int hh = h + dy;
        if (hh < 0 || hh > 63) continue;
        const float* row = qc + hh * 64;
        float ka = (dy == -1) ? k0 : (dy == 0) ? k3 : k6;
        float kb = (dy == -1) ? k1 : (dy == 0) ? k4 : k7;
        float kc = (dy == -1) ? k2 : (dy == 0) ? k5 : k8;
        // load the 6 pixels covering w0-1 .. w0+4
        float x[6];
#pragma unroll
        for (int i = 0; i < 6; i++) {
            int ww = w0 - 1 + i;
            x[i] = (ww >= 0 && ww <= 63) ? row[ww] : 0.0f;
        }
#pragma unroll
        for (int i = 0; i < 4; i++) {
            acc[i] = fmaf(ka, x[i], acc[i]);
            acc[i] = fmaf(kb, x[i + 1], acc[i]);
            acc[i] = fmaf(kc, x[i + 2], acc[i]);
        }
    }
#pragma unroll
    for (int i = 0; i < 4; i++) oc[pix0 + i] = acc[i];
}

// ---------------------------------------------------------------------------
// Launch
// ---------------------------------------------------------------------------
extern "C" void kernel_launch(void* const* d_in, const int* in_sizes, int n_in,
                              void* d_out, int out_size)
{
    const float* e_f    = (const float*)d_in[0];
    const float* e_g    = (const float*)d_in[1];
    // d_in[2] l_feat, d_in[3] l_mask: unused by the reference
    const float* ln_f_g = (const float*)d_in[4];
    const float* ln_f_b = (const float*)d_in[5];
    const float* ln_g_g = (const float*)d_in[6];
    const float* ln_g_b = (const float*)d_in[7];
    const float* wq     = (const float*)d_in[8];
    const float* bq     = (const float*)d_in[9];
    const float* wk     = (const float*)d_in[10];
    const float* bk     = (const float*)d_in[11];
    const float* wv     = (const float*)d_in[12];
    const float* bv     = (const float*)d_in[13];
    const float* wo     = (const float*)d_in[14];
    const float* bo     = (const float*)d_in[15];
    const float* dwk    = (const float*)d_in[16];
    const float* efp_w  = (const float*)d_in[17];
    const float* efp_b  = (const float*)d_in[18];
    const float* outc_w = (const float*)d_in[19];
    const float* outc_b = (const float*)d_in[20];
    const float* bn_g   = (const float*)d_in[21];
    const float* bn_b   = (const float*)d_in[22];
    const float* bn_m   = (const float*)d_in[23];
    const float* bn_v   = (const float*)d_in[24];
    float* out = (float*)d_out;

    prep_kernel<<<4, 256>>>(wq, bq, ln_f_g, ln_f_b,
                            wk, bk, ln_g_g, ln_g_b,
                            wv, bv, outc_b, bn_g, bn_b, bn_m, bn_v);
    stats_kernel<0><<<128, 256>>>(e_f);
    stats_kernel<1><<<128, 256>>>(e_g);

    dim3 gg(64, 4, 8);
    gemm_kernel<0><<<gg, 256>>>(nullptr, e_f, nullptr, nullptr, 512);   // Q
    gemm_kernel<1><<<gg, 256>>>(nullptr, e_g, nullptr, nullptr, 256);   // K
    gemm_kernel<2><<<gg, 256>>>(nullptr, e_g, nullptr, nullptr, 256);   // V

    pool_kernel<<<32, 256>>>();
    attn_kernel<<<dim3(16, 8), 256>>>();
    dwadd_kernel<<<dim3(4, 2048), 256>>>(dwk);

    gemm_kernel<3><<<gg, 256>>>(wo,     nullptr, bo,    nullptr, 256);  // comb = wo(combined)
    gemm_kernel<4><<<gg, 256>>>(efp_w,  e_f,     efp_b, nullptr, 512);  // efp
    gemm_kernel<5><<<gg, 256>>>(outc_w, nullptr, nullptr, out,   256);  // gated + BN + ReLU
}